// round 16
// baseline (speedup 1.0000x reference)
#include <cuda_runtime.h>
#include <cuda_fp16.h>
#include <math.h>
#include <stdint.h>

#define BB 4
#define SS 2048
#define DM 1024
#define HH 16
#define DH 64
#define BH (BB*HH)          // 64
#define MROWS (BB*SS)       // 8192

// Q pre-scale: d^-0.5 * log2(e) (softmax in exp2 domain)
#define QSCALE (0.125f * 1.44269504088896f)

// ---------------------------------------------------------------------------
// Scratch (alloc-free rule: __device__ globals)
// ---------------------------------------------------------------------------
__device__ uint32_t g_maskbits[(size_t)SS * (SS / 32)];   // bit-packed mask_aft
__device__ __half   g_Qh[(size_t)BH * SS * DH];           // Q (pre-scaled)
__device__ __half   g_Kh[(size_t)BH * SS * DH];           // K
__device__ __half   g_Vh[(size_t)BH * SS * DH];           // V
__device__ __half   g_Ah[(size_t)MROWS * DM];             // activations (X, later O)
__device__ __half   g_Wh[4][(size_t)DM * DM];             // weights [n][k] (Wq|Wk|Wv|Wo)

// ---------------------------------------------------------------------------
// PTX helpers
// ---------------------------------------------------------------------------
__device__ __forceinline__ uint32_t smem_u32(const void* p) {
    uint32_t a;
    asm("{ .reg .u64 t; cvta.to.shared.u64 t, %1; cvt.u32.u64 %0, t; }" : "=r"(a) : "l"(p));
    return a;
}
__device__ __forceinline__ void ldsm4(uint32_t* r, uint32_t addr) {
    asm volatile("ldmatrix.sync.aligned.m8n8.x4.shared.b16 {%0,%1,%2,%3}, [%4];"
        : "=r"(r[0]), "=r"(r[1]), "=r"(r[2]), "=r"(r[3]) : "r"(addr));
}
__device__ __forceinline__ void ldsm4t(uint32_t* r, uint32_t addr) {
    asm volatile("ldmatrix.sync.aligned.m8n8.x4.trans.shared.b16 {%0,%1,%2,%3}, [%4];"
        : "=r"(r[0]), "=r"(r[1]), "=r"(r[2]), "=r"(r[3]) : "r"(addr));
}
__device__ __forceinline__ void mma16816(float* c, const uint32_t* a, const uint32_t* b) {
    asm volatile(
        "mma.sync.aligned.m16n8k16.row.col.f32.f16.f16.f32 "
        "{%0,%1,%2,%3}, {%4,%5,%6,%7}, {%8,%9}, {%0,%1,%2,%3};"
        : "+f"(c[0]), "+f"(c[1]), "+f"(c[2]), "+f"(c[3])
        : "r"(a[0]), "r"(a[1]), "r"(a[2]), "r"(a[3]), "r"(b[0]), "r"(b[1]));
}
__device__ __forceinline__ uint32_t pack_h2(float a, float b) {
    return (uint32_t)__half_as_ushort(__float2half_rn(a)) |
           ((uint32_t)__half_as_ushort(__float2half_rn(b)) << 16);
}
__device__ __forceinline__ void cpa16(uint32_t smem, const void* g) {
    asm volatile("cp.async.cg.shared.global [%0], [%1], 16;" :: "r"(smem), "l"(g));
}
#define CP_COMMIT() asm volatile("cp.async.commit_group;" ::: "memory")
#define CP_WAIT1()  asm volatile("cp.async.wait_group 1;" ::: "memory")
#define CP_WAIT0()  asm volatile("cp.async.wait_group 0;" ::: "memory")

// ---------------------------------------------------------------------------
// pack mask_aft into bits (1 = masked). Element width detected from mask_bef
// (triu(k=1): byte[1]==1 iff 1-byte bools).
// ---------------------------------------------------------------------------
__global__ __launch_bounds__(256) void pack_mask_k(const unsigned char* __restrict__ m,
                                                   const unsigned char* __restrict__ mbef)
{
    const int idx = blockIdx.x * 256 + threadIdx.x;
    const int row = idx >> 6;
    const int grp = idx & 63;
    uint32_t bits = 0;
    if (mbef[1] != 1) {                                    // 4-byte elements
        const uint4* p = (const uint4*)((const uint32_t*)m + (size_t)row * SS + grp * 32);
#pragma unroll
        for (int j = 0; j < 8; j++) {
            uint4 w = p[j];
            bits |= (w.x ? 1u : 0u) << (j * 4 + 0);
            bits |= (w.y ? 1u : 0u) << (j * 4 + 1);
            bits |= (w.z ? 1u : 0u) << (j * 4 + 2);
            bits |= (w.w ? 1u : 0u) << (j * 4 + 3);
        }
    } else {                                               // 1-byte bools
        const unsigned char* p = m + (size_t)row * SS + grp * 32;
#pragma unroll
        for (int j = 0; j < 32; j++) bits |= (p[j] ? 1u : 0u) << j;
    }
    g_maskbits[(size_t)row * 64 + grp] = bits;
}

// fp32 Xq -> fp16
__global__ __launch_bounds__(256) void conv_split_k(const float* __restrict__ A)
{
    size_t i = ((size_t)blockIdx.x * 256 + threadIdx.x) * 4;
    float4 v = *(const float4*)(A + i);
    *(uint2*)(g_Ah + i) = make_uint2(pack_h2(v.x, v.y), pack_h2(v.z, v.w));
}

// W[k][n] fp32 -> g_Wh[z][n][k] fp16; blockIdx.z selects which weight
__global__ __launch_bounds__(256) void conv_wsplit_k(const float* __restrict__ W0,
                                                     const float* __restrict__ W1,
                                                     const float* __restrict__ W2,
                                                     const float* __restrict__ W3)
{
    __shared__ float t[32][33];
    const float* Ws[4] = {W0, W1, W2, W3};
    const float* W = Ws[blockIdx.z];
    int tx = threadIdx.x & 31, ty = threadIdx.x >> 5;
    int n0 = blockIdx.x * 32, k0 = blockIdx.y * 32;
#pragma unroll
    for (int j = 0; j < 4; j++)
        t[ty + 8 * j][tx] = W[(size_t)(k0 + ty + 8 * j) * DM + n0 + tx];
    __syncthreads();
    __half* Ho = g_Wh[blockIdx.z];
#pragma unroll
    for (int j = 0; j < 4; j++) {
        int nl = ty + 8 * j;
        Ho[(size_t)(n0 + nl) * DM + k0 + tx] = __float2half_rn(t[tx][nl]);
    }
}

// ---------------------------------------------------------------------------
// HMMA GEMM, fp16 1-term. Block 128x128, BK=32, 8 warps (warp tile 64m x 32n),
// cp.async 3-stage pipeline, 2 CTAs/SM (16 warps/SM).
// MODE 0: fused Q|K|V (N=3072, g_Wh[0..2]); Q cols scaled.
// MODE 3: fp32 C out (A = O in g_Ah, B = g_Wh[3]).
// ---------------------------------------------------------------------------
#define RS 80
#define TILE_B (128 * RS)
#define STAGE_B (2 * TILE_B)        // A + B tile
#define GSMEM (3 * STAGE_B)         // 61440

template<int MODE>
__global__ __launch_bounds__(256, 2) void gemm_tc(float* __restrict__ C)
{
    extern __shared__ char sm_[];
    const int tid  = threadIdx.x;
    const int lane = tid & 31;
    const int wid  = tid >> 5;        // 0..7
    const int wm   = wid & 1;         // m: 2 x 64
    const int wn   = wid >> 1;        // n: 4 x 32
    const int n0   = blockIdx.x * 128;
    const int m0   = blockIdx.y * 128;

    const uint32_t sb = smem_u32(sm_);

    const __half* gah = g_Ah;
    const __half* gbh = (MODE == 0) ? g_Wh[0] : g_Wh[3];

    // per-thread load slots: tile = 128 rows x 4 chunks(16B) = 512; 256 thr -> 2 each
    int lr_[2], lc_[2];
#pragma unroll
    for (int i = 0; i < 2; i++) {
        int q = tid + i * 256;
        lr_[i] = q >> 2;
        lc_[i] = q & 3;
    }

    float acc[4][4][4];
#pragma unroll
    for (int i = 0; i < 4; i++)
#pragma unroll
        for (int j = 0; j < 4; j++)
#pragma unroll
            for (int v = 0; v < 4; v++) acc[i][j][v] = 0.f;

    const int a_row = wm * 64 + (lane & 15);
    const int a_chk = (lane >> 4);
    const int b_row = wn * 32 + (lane & 7) + ((lane >> 4) << 3);
    const int b_chk = (lane >> 3) & 1;

    auto issue = [&](int k0, int buf) {
        uint32_t st = sb + buf * STAGE_B;
#pragma unroll
        for (int i = 0; i < 2; i++) {
            cpa16(st + 0*TILE_B + lr_[i]*RS + lc_[i]*16,
                  gah + (size_t)(m0 + lr_[i]) * DM + k0 + lc_[i]*8);
            cpa16(st + 1*TILE_B + lr_[i]*RS + lc_[i]*16,
                  gbh + (size_t)(n0 + lr_[i]) * DM + k0 + lc_[i]*8);
        }
    };

    issue(0, 0);  CP_COMMIT();
    issue(32, 1); CP_COMMIT();

    for (int kt = 0; kt < 32; kt++) {
        if (kt < 30) CP_WAIT1(); else CP_WAIT0();
        __syncthreads();

        const uint32_t stu = sb + (kt % 3) * STAGE_B;
#pragma unroll
        for (int s = 0; s < 2; s++) {
            const uint32_t koff = s * 32;
            uint32_t af[4][4];
#pragma unroll
            for (int mf = 0; mf < 4; mf++) {
                uint32_t ra = (uint32_t)((a_row + mf * 16) * RS + koff + a_chk * 16);
                ldsm4(af[mf], stu + 0*TILE_B + ra);
            }
            uint32_t bh[4][2];
#pragma unroll
            for (int nf2 = 0; nf2 < 2; nf2++) {
                uint32_t rb = (uint32_t)((b_row + nf2 * 16) * RS + koff + b_chk * 16);
                uint32_t t[4];
                ldsm4(t, stu + 1*TILE_B + rb);
                bh[nf2*2][0] = t[0]; bh[nf2*2][1] = t[1];
                bh[nf2*2+1][0] = t[2]; bh[nf2*2+1][1] = t[3];
            }
#pragma unroll
            for (int mf = 0; mf < 4; mf++)
#pragma unroll
                for (int nf = 0; nf < 4; nf++)
                    mma16816(acc[mf][nf], af[mf], bh[nf]);
        }

        if (kt + 2 < 32) {
            issue((kt + 2) * 32, (kt + 2) % 3);
            CP_COMMIT();
        }
    }

    const int lr  = lane >> 2;
    const int lc2 = (lane & 3) * 2;
#pragma unroll
    for (int mf = 0; mf < 4; mf++) {
#pragma unroll
        for (int nf = 0; nf < 4; nf++) {
            int row = m0 + wm * 64 + mf * 16 + lr;
            int col = n0 + wn * 32 + nf * 8 + lc2;
            if (MODE == 0) {
                int b_ = row >> 11, s_ = row & 2047;
                int which = col >> 10;                 // 0=Q, 1=K, 2=V
                __half* dst = (which == 0) ? g_Qh : (which == 1) ? g_Kh : g_Vh;
                float sc = (which == 0) ? QSCALE : 1.0f;
                int c2 = col & 1023;
                int h_ = c2 >> 6, d_ = c2 & 63;
                size_t idx0 = ((size_t)(b_ * HH + h_) * SS + s_) * DH + d_;
                size_t idx1 = idx0 + (size_t)8 * DH;
                *(uint32_t*)(dst + idx0) = pack_h2(acc[mf][nf][0] * sc, acc[mf][nf][1] * sc);
                *(uint32_t*)(dst + idx1) = pack_h2(acc[mf][nf][2] * sc, acc[mf][nf][3] * sc);
            } else {
                *(float2*)(C + (size_t)row * DM + col) = make_float2(acc[mf][nf][0], acc[mf][nf][1]);
                *(float2*)(C + (size_t)(row + 8) * DM + col) = make_float2(acc[mf][nf][2], acc[mf][nf][3]);
            }
        }
    }
}

// ---------------------------------------------------------------------------
// HMMA flash attention, fp16. CTA = 128 q-rows, 4 warps x (32q x 64k),
// cp.async 3-stage KV pipeline, 2 CTAs/SM. Per-warp causal early-out.
// (exact R14 version)
// ---------------------------------------------------------------------------
#define ARS 144
#define QTILE_B (128 * ARS)                        // 18432
#define KVT_B (64 * ARS)                           // 9216
#define KVSTAGE_B (2 * KVT_B)                      // Kh, Vh = 18432
#define ATT_SMEM (QTILE_B + 3 * KVSTAGE_B)         // 73728

__global__ __launch_bounds__(128, 2) void attn_k()
{
    extern __shared__ char asm_[];
    const int tid  = threadIdx.x;                   // 0..127
    const int lane = tid & 31;
    const int wid  = tid >> 5;                      // 0..3, rows wid*32..+31
    const int qt   = (int)gridDim.x - 1 - (int)blockIdx.x;   // heavy first
    const int bh   = blockIdx.y;
    const int qbase = qt * 128;

    const int g  = lane >> 2;
    const int t2 = (lane & 3) * 2;

    const uint32_t sb  = smem_u32(asm_);
    const uint32_t sQ  = sb;
    const uint32_t sKV = sb + QTILE_B;

    const size_t boff = (size_t)bh * SS * DH;
    const __half* Qh = g_Qh + boff;
    const __half* kvsrc[2] = {g_Kh + boff, g_Vh + boff};

    int kr_[8], kc_[8], ka_[8];
#pragma unroll
    for (int i = 0; i < 8; i++) {
        const int a  = i >> 2;
        const int q2 = tid + (i & 3) * 128;
        ka_[i] = a;
        kr_[i] = q2 >> 3;
        kc_[i] = q2 & 7;
    }
    auto issue_kv = [&](int ktbase, int buf) {
        uint32_t st = sKV + buf * KVSTAGE_B;
#pragma unroll
        for (int i = 0; i < 8; i++)
            cpa16(st + ka_[i] * KVT_B + kr_[i] * ARS + kc_[i] * 16,
                  kvsrc[ka_[i]] + (size_t)(ktbase + kr_[i]) * DH + kc_[i] * 8);
    };

    const int ktmax = 2 * qt + 1;

    issue_kv(0, 0);  CP_COMMIT();
    issue_kv(64, 1); CP_COMMIT();

#pragma unroll
    for (int i = 0; i < 8; i++) {
        const int q2 = tid + i * 128;
        const int r  = q2 >> 3, ch = q2 & 7;
        *(uint4*)(asm_ + r * ARS + ch * 16) =
            *(const uint4*)(Qh + (size_t)(qbase + r) * DH + ch * 8);
    }
    __syncthreads();

    const int a_row = wid * 32 + (lane & 15);
    const int a_chk = lane >> 4;
    uint32_t qf[2][4][4];
#pragma unroll
    for (int mf = 0; mf < 2; mf++)
#pragma unroll
        for (int s = 0; s < 4; s++) {
            uint32_t ra = (uint32_t)((a_row + mf * 16) * ARS + s * 32 + a_chk * 16);
            ldsm4(qf[mf][s], sQ + ra);
        }

    const int b_row = (lane & 7) + ((lane >> 4) << 3);
    const int b_chk = (lane >> 3) & 1;

    float m_[4], l_[4];
#pragma unroll
    for (int j = 0; j < 4; j++) { m_[j] = -INFINITY; l_[j] = 0.f; }
    float o[2][8][4];
#pragma unroll
    for (int mf = 0; mf < 2; mf++)
#pragma unroll
        for (int nf = 0; nf < 8; nf++)
#pragma unroll
            for (int e = 0; e < 4; e++) o[mf][nf][e] = 0.f;

    int qrow[4];
#pragma unroll
    for (int j = 0; j < 4; j++) qrow[j] = qbase + wid * 32 + j * 8 + g;
    const int wlast = qbase + wid * 32 + 31;

    for (int kt = 0; kt <= ktmax; kt++) {
        const int ktbase = kt * 64;
        if (kt < ktmax) CP_WAIT1(); else CP_WAIT0();
        __syncthreads();
        const uint32_t stg = sKV + (kt % 3) * KVSTAGE_B;

        if (ktbase <= wlast) {
            uint2 mb[4];
#pragma unroll
            for (int j = 0; j < 4; j++)
                mb[j] = *(const uint2*)(g_maskbits + (size_t)qrow[j] * 64 + (ktbase >> 5));

            float sc[2][8][4];
#pragma unroll
            for (int mf = 0; mf < 2; mf++)
#pragma unroll
                for (int nf = 0; nf < 8; nf++)
#pragma unroll
                    for (int e = 0; e < 4; e++) sc[mf][nf][e] = 0.f;

#pragma unroll
            for (int s = 0; s < 4; s++) {
                uint32_t bf[8][2];
#pragma unroll
                for (int nf2 = 0; nf2 < 4; nf2++) {
                    uint32_t rb = (uint32_t)((b_row + nf2 * 16) * ARS + s * 32 + b_chk * 16);
                    uint32_t t[4];
                    ldsm4(t, stg + rb);
                    bf[nf2*2][0] = t[0]; bf[nf2*2][1] = t[1];
                    bf[nf2*2+1][0] = t[2]; bf[nf2*2+1][1] = t[3];
                }
#pragma unroll
                for (int nf = 0; nf < 8; nf++) {
                    mma16816(sc[0][nf], qf[0][s], bf[nf]);
                    mma16816(sc[1][nf], qf[1][s], bf[nf]);
                }
            }

            if (ktbase + 63 > qbase + wid * 32) {
#pragma unroll
                for (int mf = 0; mf < 2; mf++)
#pragma unroll
                    for (int nf = 0; nf < 8; nf++) {
                        int kg = ktbase + nf * 8 + t2;
                        if (kg     > qrow[2*mf])   sc[mf][nf][0] = -INFINITY;
                        if (kg + 1 > qrow[2*mf])   sc[mf][nf][1] = -INFINITY;
                        if (kg     > qrow[2*mf+1]) sc[mf][nf][2] = -INFINITY;
                        if (kg + 1 > qrow[2*mf+1]) sc[mf][nf][3] = -INFINITY;
                    }
            }

#pragma unroll
            for (int j = 0; j < 4; j++) {
                const int mf = j >> 1, e0 = (j & 1) * 2, e1 = e0 + 1;
                float mx = -INFINITY;
#pragma unroll
                for (int nf = 0; nf < 8; nf++)
                    mx = fmaxf(mx, fmaxf(sc[mf][nf][e0], sc[mf][nf][e1]));
                mx = fmaxf(mx, __shfl_xor_sync(0xffffffffu, mx, 1));
                mx = fmaxf(mx, __shfl_xor_sync(0xffffffffu, mx, 2));
                float mn = fmaxf(m_[j], mx);
                float al = exp2f(m_[j] - mn);
                m_[j] = mn;
                float ss = 0.f;
#pragma unroll
                for (int nf = 0; nf < 8; nf++) {
                    sc[mf][nf][e0] = exp2f(sc[mf][nf][e0] - mn);
                    sc[mf][nf][e1] = exp2f(sc[mf][nf][e1] - mn);
                    ss += sc[mf][nf][e0] + sc[mf][nf][e1];
                }
                ss += __shfl_xor_sync(0xffffffffu, ss, 1);
                ss += __shfl_xor_sync(0xffffffffu, ss, 2);
                l_[j] = l_[j] * al + ss;
#pragma unroll
                for (int nf = 0; nf < 8; nf++) {
                    o[mf][nf][e0] *= al;
                    o[mf][nf][e1] *= al;
                }
            }

#pragma unroll
            for (int mf = 0; mf < 2; mf++)
#pragma unroll
                for (int nf = 0; nf < 8; nf++) {
                    const int sh = (nf & 3) * 8 + t2;
                    uint32_t w0 = ((nf < 4) ? mb[2*mf].x   : mb[2*mf].y)   >> sh;
                    uint32_t w1 = ((nf < 4) ? mb[2*mf+1].x : mb[2*mf+1].y) >> sh;
                    if (w0 & 1u) sc[mf][nf][0] = 0.f;
                    if (w0 & 2u) sc[mf][nf][1] = 0.f;
                    if (w1 & 1u) sc[mf][nf][2] = 0.f;
                    if (w1 & 2u) sc[mf][nf][3] = 0.f;
                }

#pragma unroll
            for (int s = 0; s < 4; s++) {
                uint32_t ap[2][4];
#pragma unroll
                for (int mf = 0; mf < 2; mf++) {
                    ap[mf][0] = pack_h2(sc[mf][2*s][0],   sc[mf][2*s][1]);
                    ap[mf][1] = pack_h2(sc[mf][2*s][2],   sc[mf][2*s][3]);
                    ap[mf][2] = pack_h2(sc[mf][2*s+1][0], sc[mf][2*s+1][1]);
                    ap[mf][3] = pack_h2(sc[mf][2*s+1][2], sc[mf][2*s+1][3]);
                }
                uint32_t vf[8][2];
                const uint32_t vrow = (uint32_t)((s * 16 + (lane & 15)) * ARS + ((lane >> 4) << 3) * 2);
#pragma unroll
                for (int nb2 = 0; nb2 < 4; nb2++) {
                    uint32_t rb = vrow + (uint32_t)(nb2 * 32);
                    uint32_t t[4];
                    ldsm4t(t, stg + KVT_B + rb);
                    vf[nb2*2][0] = t[0]; vf[nb2*2][1] = t[1];
                    vf[nb2*2+1][0] = t[2]; vf[nb2*2+1][1] = t[3];
                }
#pragma unroll
                for (int nf = 0; nf < 8; nf++) {
                    mma16816(o[0][nf], ap[0], vf[nf]);
                    mma16816(o[1][nf], ap[1], vf[nf]);
                }
            }
        }

        if (kt + 2 <= ktmax) {
            issue_kv((kt + 2) * 64, (kt + 2) % 3);
            CP_COMMIT();
        }
    }

    const int b_ = bh >> 4, h_ = bh & 15;
    float inv[4];
#pragma unroll
    for (int j = 0; j < 4; j++) inv[j] = 1.0f / l_[j];
#pragma unroll
    for (int mf = 0; mf < 2; mf++) {
        const size_t rm0 = (size_t)(b_ * SS + qrow[2*mf])   * DM + h_ * DH + t2;
        const size_t rm1 = (size_t)(b_ * SS + qrow[2*mf+1]) * DM + h_ * DH + t2;
#pragma unroll
        for (int nf = 0; nf < 8; nf++) {
            *(uint32_t*)(g_Ah + rm0 + nf * 8) = pack_h2(o[mf][nf][0] * inv[2*mf],   o[mf][nf][1] * inv[2*mf]);
            *(uint32_t*)(g_Ah + rm1 + nf * 8) = pack_h2(o[mf][nf][2] * inv[2*mf+1], o[mf][nf][3] * inv[2*mf+1]);
        }
    }
}

// ---------------------------------------------------------------------------
extern "C" void kernel_launch(void* const* d_in, const int* in_sizes, int n_in,
                              void* d_out, int out_size)
{
    const float* Xq = (const float*)d_in[0];
    const unsigned char* mask_bef = (const unsigned char*)d_in[1];
    const unsigned char* mask_aft = (const unsigned char*)d_in[2];
    const float* Wq = (const float*)d_in[3];
    const float* Wk = (const float*)d_in[4];
    const float* Wv = (const float*)d_in[5];
    const float* Wo = (const float*)d_in[6];
    float* out = (float*)d_out;

    cudaFuncSetAttribute(attn_k, cudaFuncAttributeMaxDynamicSharedMemorySize, ATT_SMEM);
    cudaFuncSetAttribute(gemm_tc<0>, cudaFuncAttributeMaxDynamicSharedMemorySize, GSMEM);
    cudaFuncSetAttribute(gemm_tc<3>, cudaFuncAttributeMaxDynamicSharedMemorySize, GSMEM);

    dim3 blkA(128);
    dim3 blk(256);
    dim3 gQKV(24, 64);           // N=3072 fused Q|K|V
    dim3 gO(8, 64);              // N=1024
    dim3 gW(32, 32, 4);          // all four weights in one launch

    pack_mask_k<<<SS * (SS / 32) / 256, blk>>>(mask_aft, mask_bef);
    conv_split_k<<<MROWS * DM / 4 / 256, blk>>>(Xq);
    conv_wsplit_k<<<gW, blk>>>(Wq, Wk, Wv, Wo);
    gemm_tc<0><<<gQKV, blk, GSMEM>>>(nullptr);
    attn_k<<<dim3(16, BH), blkA, ATT_SMEM>>>();
    gemm_tc<3><<<gO, blk, GSMEM>>>(out);
}

// round 17
// speedup vs baseline: 1.0804x; 1.0804x over previous
#include <cuda_runtime.h>
#include <cuda_fp16.h>
#include <math.h>
#include <stdint.h>

#define BB 4
#define SS 2048
#define DM 1024
#define HH 16
#define DH 64
#define BH (BB*HH)          // 64
#define MROWS (BB*SS)       // 8192

// Q pre-scale: d^-0.5 * log2(e) (softmax in exp2 domain)
#define QSCALE (0.125f * 1.44269504088896f)

// ---------------------------------------------------------------------------
// Scratch (alloc-free rule: __device__ globals)
// ---------------------------------------------------------------------------
__device__ uint32_t g_maskbits[(size_t)SS * (SS / 32)];   // bit-packed mask_aft
__device__ __half   g_Qh[(size_t)BH * SS * DH];           // Q (pre-scaled)
__device__ __half   g_Kh[(size_t)BH * SS * DH];           // K
__device__ __half   g_Vh[(size_t)BH * SS * DH];           // V
__device__ __half   g_Ah[(size_t)MROWS * DM];             // activations (X, later O)
__device__ __half   g_Wh[4][(size_t)DM * DM];             // weights [n][k] (Wq|Wk|Wv|Wo)

// ---------------------------------------------------------------------------
// PTX helpers
// ---------------------------------------------------------------------------
__device__ __forceinline__ uint32_t smem_u32(const void* p) {
    uint32_t a;
    asm("{ .reg .u64 t; cvta.to.shared.u64 t, %1; cvt.u32.u64 %0, t; }" : "=r"(a) : "l"(p));
    return a;
}
__device__ __forceinline__ void ldsm4(uint32_t* r, uint32_t addr) {
    asm volatile("ldmatrix.sync.aligned.m8n8.x4.shared.b16 {%0,%1,%2,%3}, [%4];"
        : "=r"(r[0]), "=r"(r[1]), "=r"(r[2]), "=r"(r[3]) : "r"(addr));
}
__device__ __forceinline__ void ldsm4t(uint32_t* r, uint32_t addr) {
    asm volatile("ldmatrix.sync.aligned.m8n8.x4.trans.shared.b16 {%0,%1,%2,%3}, [%4];"
        : "=r"(r[0]), "=r"(r[1]), "=r"(r[2]), "=r"(r[3]) : "r"(addr));
}
__device__ __forceinline__ void mma16816(float* c, const uint32_t* a, const uint32_t* b) {
    asm volatile(
        "mma.sync.aligned.m16n8k16.row.col.f32.f16.f16.f32 "
        "{%0,%1,%2,%3}, {%4,%5,%6,%7}, {%8,%9}, {%0,%1,%2,%3};"
        : "+f"(c[0]), "+f"(c[1]), "+f"(c[2]), "+f"(c[3])
        : "r"(a[0]), "r"(a[1]), "r"(a[2]), "r"(a[3]), "r"(b[0]), "r"(b[1]));
}
__device__ __forceinline__ uint32_t pack_h2(float a, float b) {
    return (uint32_t)__half_as_ushort(__float2half_rn(a)) |
           ((uint32_t)__half_as_ushort(__float2half_rn(b)) << 16);
}
__device__ __forceinline__ void cpa16(uint32_t smem, const void* g) {
    asm volatile("cp.async.cg.shared.global [%0], [%1], 16;" :: "r"(smem), "l"(g));
}
#define CP_COMMIT() asm volatile("cp.async.commit_group;" ::: "memory")
#define CP_WAIT1()  asm volatile("cp.async.wait_group 1;" ::: "memory")
#define CP_WAIT0()  asm volatile("cp.async.wait_group 0;" ::: "memory")

// ---------------------------------------------------------------------------
// Fused prep: conv_wsplit (blocks 0..4095), conv_split (4096..12287),
// pack_mask (12288..12799). All independent; one launch fills the chip.
// ---------------------------------------------------------------------------
__global__ __launch_bounds__(256) void prep_k(const float* __restrict__ Xq,
                                              const unsigned char* __restrict__ mask_aft,
                                              const unsigned char* __restrict__ mask_bef,
                                              const float* __restrict__ W0,
                                              const float* __restrict__ W1,
                                              const float* __restrict__ W2,
                                              const float* __restrict__ W3)
{
    __shared__ float t[32][33];
    const int b = blockIdx.x;

    if (b < 4096) {
        // ---- weight transpose+convert: W[k][n] fp32 -> g_Wh[z][n][k] fp16 ----
        const float* Ws[4] = {W0, W1, W2, W3};
        const int z  = b >> 10;
        const int x  = b & 31;
        const int y  = (b >> 5) & 31;
        const float* W = Ws[z];
        int tx = threadIdx.x & 31, ty = threadIdx.x >> 5;
        int n0 = x * 32, k0 = y * 32;
#pragma unroll
        for (int j = 0; j < 4; j++)
            t[ty + 8 * j][tx] = W[(size_t)(k0 + ty + 8 * j) * DM + n0 + tx];
        __syncthreads();
        __half* Ho = g_Wh[z];
#pragma unroll
        for (int j = 0; j < 4; j++) {
            int nl = ty + 8 * j;
            Ho[(size_t)(n0 + nl) * DM + k0 + tx] = __float2half_rn(t[tx][nl]);
        }
    } else if (b < 12288) {
        // ---- activation convert: fp32 Xq -> fp16 g_Ah ----
        size_t i = ((size_t)(b - 4096) * 256 + threadIdx.x) * 4;
        float4 v = *(const float4*)(Xq + i);
        *(uint2*)(g_Ah + i) = make_uint2(pack_h2(v.x, v.y), pack_h2(v.z, v.w));
    } else {
        // ---- mask bit-pack (width from mask_bef: triu(k=1), byte[1]==1 iff bool) ----
        const int idx = (b - 12288) * 256 + threadIdx.x;
        const int row = idx >> 6;
        const int grp = idx & 63;
        uint32_t bits = 0;
        if (mask_bef[1] != 1) {                            // 4-byte elements
            const uint4* p = (const uint4*)((const uint32_t*)mask_aft + (size_t)row * SS + grp * 32);
#pragma unroll
            for (int j = 0; j < 8; j++) {
                uint4 w = p[j];
                bits |= (w.x ? 1u : 0u) << (j * 4 + 0);
                bits |= (w.y ? 1u : 0u) << (j * 4 + 1);
                bits |= (w.z ? 1u : 0u) << (j * 4 + 2);
                bits |= (w.w ? 1u : 0u) << (j * 4 + 3);
            }
        } else {                                           // 1-byte bools
            const unsigned char* p = mask_aft + (size_t)row * SS + grp * 32;
#pragma unroll
            for (int j = 0; j < 32; j++) bits |= (p[j] ? 1u : 0u) << j;
        }
        g_maskbits[(size_t)row * 64 + grp] = bits;
    }
}

// ---------------------------------------------------------------------------
// HMMA GEMM, fp16 1-term. Block 128x128, BK=32, 4 warps (warp tile 64x64),
// cp.async 3-stage pipeline, 2 CTAs/SM. (exact R14 config)
// MODE 0: fused Q|K|V (N=3072, g_Wh[0..2]); Q cols scaled.
// MODE 3: fp32 C out (A = O in g_Ah, B = g_Wh[3]).
// ---------------------------------------------------------------------------
#define RS 80
#define TILE_B (128 * RS)
#define STAGE_B (2 * TILE_B)        // A + B tile
#define GSMEM (3 * STAGE_B)         // 61440

template<int MODE>
__global__ __launch_bounds__(128, 2) void gemm_tc(float* __restrict__ C)
{
    extern __shared__ char sm_[];
    const int tid  = threadIdx.x;
    const int lane = tid & 31;
    const int wid  = tid >> 5;        // 0..3
    const int wm   = wid & 1;         // m: 2 x 64
    const int wn   = wid >> 1;        // n: 2 x 64
    const int n0   = blockIdx.x * 128;
    const int m0   = blockIdx.y * 128;

    const uint32_t sb = smem_u32(sm_);

    const __half* gah = g_Ah;
    const __half* gbh = (MODE == 0) ? g_Wh[0] : g_Wh[3];

    int lr_[4], lc_[4];
#pragma unroll
    for (int i = 0; i < 4; i++) {
        int q = tid + i * 128;
        lr_[i] = q >> 2;
        lc_[i] = q & 3;
    }

    float acc[4][8][4];
#pragma unroll
    for (int i = 0; i < 4; i++)
#pragma unroll
        for (int j = 0; j < 8; j++)
#pragma unroll
            for (int v = 0; v < 4; v++) acc[i][j][v] = 0.f;

    const int a_row = wm * 64 + (lane & 15);
    const int a_chk = (lane >> 4);
    const int b_row = wn * 64 + (lane & 7) + ((lane >> 4) << 3);
    const int b_chk = (lane >> 3) & 1;

    auto issue = [&](int k0, int buf) {
        uint32_t st = sb + buf * STAGE_B;
#pragma unroll
        for (int i = 0; i < 4; i++) {
            cpa16(st + 0*TILE_B + lr_[i]*RS + lc_[i]*16,
                  gah + (size_t)(m0 + lr_[i]) * DM + k0 + lc_[i]*8);
            cpa16(st + 1*TILE_B + lr_[i]*RS + lc_[i]*16,
                  gbh + (size_t)(n0 + lr_[i]) * DM + k0 + lc_[i]*8);
        }
    };

    issue(0, 0);  CP_COMMIT();
    issue(32, 1); CP_COMMIT();

    for (int kt = 0; kt < 32; kt++) {
        if (kt < 30) CP_WAIT1(); else CP_WAIT0();
        __syncthreads();

        const uint32_t stu = sb + (kt % 3) * STAGE_B;
#pragma unroll
        for (int s = 0; s < 2; s++) {
            const uint32_t koff = s * 32;
            uint32_t af[4][4];
#pragma unroll
            for (int mf = 0; mf < 4; mf++) {
                uint32_t ra = (uint32_t)((a_row + mf * 16) * RS + koff + a_chk * 16);
                ldsm4(af[mf], stu + 0*TILE_B + ra);
            }
            uint32_t bh[8][2];
#pragma unroll
            for (int nf2 = 0; nf2 < 4; nf2++) {
                uint32_t rb = (uint32_t)((b_row + nf2 * 16) * RS + koff + b_chk * 16);
                uint32_t t[4];
                ldsm4(t, stu + 1*TILE_B + rb);
                bh[nf2*2][0] = t[0]; bh[nf2*2][1] = t[1];
                bh[nf2*2+1][0] = t[2]; bh[nf2*2+1][1] = t[3];
            }
#pragma unroll
            for (int mf = 0; mf < 4; mf++)
#pragma unroll
                for (int nf = 0; nf < 8; nf++)
                    mma16816(acc[mf][nf], af[mf], bh[nf]);
        }

        if (kt + 2 < 32) {
            issue((kt + 2) * 32, (kt + 2) % 3);
            CP_COMMIT();
        }
    }

    const int lr  = lane >> 2;
    const int lc2 = (lane & 3) * 2;
#pragma unroll
    for (int mf = 0; mf < 4; mf++) {
#pragma unroll
        for (int nf = 0; nf < 8; nf++) {
            int row = m0 + wm * 64 + mf * 16 + lr;
            int col = n0 + wn * 64 + nf * 8 + lc2;
            if (MODE == 0) {
                int b_ = row >> 11, s_ = row & 2047;
                int which = col >> 10;                 // 0=Q, 1=K, 2=V
                __half* dst = (which == 0) ? g_Qh : (which == 1) ? g_Kh : g_Vh;
                float sc = (which == 0) ? QSCALE : 1.0f;
                int c2 = col & 1023;
                int h_ = c2 >> 6, d_ = c2 & 63;
                size_t idx0 = ((size_t)(b_ * HH + h_) * SS + s_) * DH + d_;
                size_t idx1 = idx0 + (size_t)8 * DH;
                *(uint32_t*)(dst + idx0) = pack_h2(acc[mf][nf][0] * sc, acc[mf][nf][1] * sc);
                *(uint32_t*)(dst + idx1) = pack_h2(acc[mf][nf][2] * sc, acc[mf][nf][3] * sc);
            } else {
                *(float2*)(C + (size_t)row * DM + col) = make_float2(acc[mf][nf][0], acc[mf][nf][1]);
                *(float2*)(C + (size_t)(row + 8) * DM + col) = make_float2(acc[mf][nf][2], acc[mf][nf][3]);
            }
        }
    }
}

// ---------------------------------------------------------------------------
// HMMA flash attention, fp16. CTA = 128 q-rows, 4 warps x (32q x 64k),
// cp.async 3-stage KV pipeline, 2 CTAs/SM. Per-warp causal early-out.
// (exact R14 version)
// ---------------------------------------------------------------------------
#define ARS 144
#define QTILE_B (128 * ARS)                        // 18432
#define KVT_B (64 * ARS)                           // 9216
#define KVSTAGE_B (2 * KVT_B)                      // Kh, Vh = 18432
#define ATT_SMEM (QTILE_B + 3 * KVSTAGE_B)         // 73728

__global__ __launch_bounds__(128, 2) void attn_k()
{
    extern __shared__ char asm_[];
    const int tid  = threadIdx.x;                   // 0..127
    const int lane = tid & 31;
    const int wid  = tid >> 5;                      // 0..3, rows wid*32..+31
    const int qt   = (int)gridDim.x - 1 - (int)blockIdx.x;   // heavy first
    const int bh   = blockIdx.y;
    const int qbase = qt * 128;

    const int g  = lane >> 2;
    const int t2 = (lane & 3) * 2;

    const uint32_t sb  = smem_u32(asm_);
    const uint32_t sQ  = sb;
    const uint32_t sKV = sb + QTILE_B;

    const size_t boff = (size_t)bh * SS * DH;
    const __half* Qh = g_Qh + boff;
    const __half* kvsrc[2] = {g_Kh + boff, g_Vh + boff};

    int kr_[8], kc_[8], ka_[8];
#pragma unroll
    for (int i = 0; i < 8; i++) {
        const int a  = i >> 2;
        const int q2 = tid + (i & 3) * 128;
        ka_[i] = a;
        kr_[i] = q2 >> 3;
        kc_[i] = q2 & 7;
    }
    auto issue_kv = [&](int ktbase, int buf) {
        uint32_t st = sKV + buf * KVSTAGE_B;
#pragma unroll
        for (int i = 0; i < 8; i++)
            cpa16(st + ka_[i] * KVT_B + kr_[i] * ARS + kc_[i] * 16,
                  kvsrc[ka_[i]] + (size_t)(ktbase + kr_[i]) * DH + kc_[i] * 8);
    };

    const int ktmax = 2 * qt + 1;

    issue_kv(0, 0);  CP_COMMIT();
    issue_kv(64, 1); CP_COMMIT();

#pragma unroll
    for (int i = 0; i < 8; i++) {
        const int q2 = tid + i * 128;
        const int r  = q2 >> 3, ch = q2 & 7;
        *(uint4*)(asm_ + r * ARS + ch * 16) =
            *(const uint4*)(Qh + (size_t)(qbase + r) * DH + ch * 8);
    }
    __syncthreads();

    const int a_row = wid * 32 + (lane & 15);
    const int a_chk = lane >> 4;
    uint32_t qf[2][4][4];
#pragma unroll
    for (int mf = 0; mf < 2; mf++)
#pragma unroll
        for (int s = 0; s < 4; s++) {
            uint32_t ra = (uint32_t)((a_row + mf * 16) * ARS + s * 32 + a_chk * 16);
            ldsm4(qf[mf][s], sQ + ra);
        }

    const int b_row = (lane & 7) + ((lane >> 4) << 3);
    const int b_chk = (lane >> 3) & 1;

    float m_[4], l_[4];
#pragma unroll
    for (int j = 0; j < 4; j++) { m_[j] = -INFINITY; l_[j] = 0.f; }
    float o[2][8][4];
#pragma unroll
    for (int mf = 0; mf < 2; mf++)
#pragma unroll
        for (int nf = 0; nf < 8; nf++)
#pragma unroll
            for (int e = 0; e < 4; e++) o[mf][nf][e] = 0.f;

    int qrow[4];
#pragma unroll
    for (int j = 0; j < 4; j++) qrow[j] = qbase + wid * 32 + j * 8 + g;
    const int wlast = qbase + wid * 32 + 31;

    for (int kt = 0; kt <= ktmax; kt++) {
        const int ktbase = kt * 64;
        if (kt < ktmax) CP_WAIT1(); else CP_WAIT0();
        __syncthreads();
        const uint32_t stg = sKV + (kt % 3) * KVSTAGE_B;

        if (ktbase <= wlast) {
            uint2 mb[4];
#pragma unroll
            for (int j = 0; j < 4; j++)
                mb[j] = *(const uint2*)(g_maskbits + (size_t)qrow[j] * 64 + (ktbase >> 5));

            float sc[2][8][4];
#pragma unroll
            for (int mf = 0; mf < 2; mf++)
#pragma unroll
                for (int nf = 0; nf < 8; nf++)
#pragma unroll
                    for (int e = 0; e < 4; e++) sc[mf][nf][e] = 0.f;

#pragma unroll
            for (int s = 0; s < 4; s++) {
                uint32_t bf[8][2];
#pragma unroll
                for (int nf2 = 0; nf2 < 4; nf2++) {
                    uint32_t rb = (uint32_t)((b_row + nf2 * 16) * ARS + s * 32 + b_chk * 16);
                    uint32_t t[4];
                    ldsm4(t, stg + rb);
                    bf[nf2*2][0] = t[0]; bf[nf2*2][1] = t[1];
                    bf[nf2*2+1][0] = t[2]; bf[nf2*2+1][1] = t[3];
                }
#pragma unroll
                for (int nf = 0; nf < 8; nf++) {
                    mma16816(sc[0][nf], qf[0][s], bf[nf]);
                    mma16816(sc[1][nf], qf[1][s], bf[nf]);
                }
            }

            if (ktbase + 63 > qbase + wid * 32) {
#pragma unroll
                for (int mf = 0; mf < 2; mf++)
#pragma unroll
                    for (int nf = 0; nf < 8; nf++) {
                        int kg = ktbase + nf * 8 + t2;
                        if (kg     > qrow[2*mf])   sc[mf][nf][0] = -INFINITY;
                        if (kg + 1 > qrow[2*mf])   sc[mf][nf][1] = -INFINITY;
                        if (kg     > qrow[2*mf+1]) sc[mf][nf][2] = -INFINITY;
                        if (kg + 1 > qrow[2*mf+1]) sc[mf][nf][3] = -INFINITY;
                    }
            }

#pragma unroll
            for (int j = 0; j < 4; j++) {
                const int mf = j >> 1, e0 = (j & 1) * 2, e1 = e0 + 1;
                float mx = -INFINITY;
#pragma unroll
                for (int nf = 0; nf < 8; nf++)
                    mx = fmaxf(mx, fmaxf(sc[mf][nf][e0], sc[mf][nf][e1]));
                mx = fmaxf(mx, __shfl_xor_sync(0xffffffffu, mx, 1));
                mx = fmaxf(mx, __shfl_xor_sync(0xffffffffu, mx, 2));
                float mn = fmaxf(m_[j], mx);
                float al = exp2f(m_[j] - mn);
                m_[j] = mn;
                float ss = 0.f;
#pragma unroll
                for (int nf = 0; nf < 8; nf++) {
                    sc[mf][nf][e0] = exp2f(sc[mf][nf][e0] - mn);
                    sc[mf][nf][e1] = exp2f(sc[mf][nf][e1] - mn);
                    ss += sc[mf][nf][e0] + sc[mf][nf][e1];
                }
                ss += __shfl_xor_sync(0xffffffffu, ss, 1);
                ss += __shfl_xor_sync(0xffffffffu, ss, 2);
                l_[j] = l_[j] * al + ss;
#pragma unroll
                for (int nf = 0; nf < 8; nf++) {
                    o[mf][nf][e0] *= al;
                    o[mf][nf][e1] *= al;
                }
            }

#pragma unroll
            for (int mf = 0; mf < 2; mf++)
#pragma unroll
                for (int nf = 0; nf < 8; nf++) {
                    const int sh = (nf & 3) * 8 + t2;
                    uint32_t w0 = ((nf < 4) ? mb[2*mf].x   : mb[2*mf].y)   >> sh;
                    uint32_t w1 = ((nf < 4) ? mb[2*mf+1].x : mb[2*mf+1].y) >> sh;
                    if (w0 & 1u) sc[mf][nf][0] = 0.f;
                    if (w0 & 2u) sc[mf][nf][1] = 0.f;
                    if (w1 & 1u) sc[mf][nf][2] = 0.f;
                    if (w1 & 2u) sc[mf][nf][3] = 0.f;
                }

#pragma unroll
            for (int s = 0; s < 4; s++) {
                uint32_t ap[2][4];
#pragma unroll
                for (int mf = 0; mf < 2; mf++) {
                    ap[mf][0] = pack_h2(sc[mf][2*s][0],   sc[mf][2*s][1]);
                    ap[mf][1] = pack_h2(sc[mf][2*s][2],   sc[mf][2*s][3]);
                    ap[mf][2] = pack_h2(sc[mf][2*s+1][0], sc[mf][2*s+1][1]);
                    ap[mf][3] = pack_h2(sc[mf][2*s+1][2], sc[mf][2*s+1][3]);
                }
                uint32_t vf[8][2];
                const uint32_t vrow = (uint32_t)((s * 16 + (lane & 15)) * ARS + ((lane >> 4) << 3) * 2);
#pragma unroll
                for (int nb2 = 0; nb2 < 4; nb2++) {
                    uint32_t rb = vrow + (uint32_t)(nb2 * 32);
                    uint32_t t[4];
                    ldsm4t(t, stg + KVT_B + rb);
                    vf[nb2*2][0] = t[0]; vf[nb2*2][1] = t[1];
                    vf[nb2*2+1][0] = t[2]; vf[nb2*2+1][1] = t[3];
                }
#pragma unroll
                for (int nf = 0; nf < 8; nf++) {
                    mma16816(o[0][nf], ap[0], vf[nf]);
                    mma16816(o[1][nf], ap[1], vf[nf]);
                }
            }
        }

        if (kt + 2 <= ktmax) {
            issue_kv((kt + 2) * 64, (kt + 2) % 3);
            CP_COMMIT();
        }
    }

    const int b_ = bh >> 4, h_ = bh & 15;
    float inv[4];
#pragma unroll
    for (int j = 0; j < 4; j++) inv[j] = 1.0f / l_[j];
#pragma unroll
    for (int mf = 0; mf < 2; mf++) {
        const size_t rm0 = (size_t)(b_ * SS + qrow[2*mf])   * DM + h_ * DH + t2;
        const size_t rm1 = (size_t)(b_ * SS + qrow[2*mf+1]) * DM + h_ * DH + t2;
#pragma unroll
        for (int nf = 0; nf < 8; nf++) {
            *(uint32_t*)(g_Ah + rm0 + nf * 8) = pack_h2(o[mf][nf][0] * inv[2*mf],   o[mf][nf][1] * inv[2*mf]);
            *(uint32_t*)(g_Ah + rm1 + nf * 8) = pack_h2(o[mf][nf][2] * inv[2*mf+1], o[mf][nf][3] * inv[2*mf+1]);
        }
    }
}

// ---------------------------------------------------------------------------
extern "C" void kernel_launch(void* const* d_in, const int* in_sizes, int n_in,
                              void* d_out, int out_size)
{
    const float* Xq = (const float*)d_in[0];
    const unsigned char* mask_bef = (const unsigned char*)d_in[1];
    const unsigned char* mask_aft = (const unsigned char*)d_in[2];
    const float* Wq = (const float*)d_in[3];
    const float* Wk = (const float*)d_in[4];
    const float* Wv = (const float*)d_in[5];
    const float* Wo = (const float*)d_in[6];
    float* out = (float*)d_out;

    cudaFuncSetAttribute(attn_k, cudaFuncAttributeMaxDynamicSharedMemorySize, ATT_SMEM);
    cudaFuncSetAttribute(gemm_tc<0>, cudaFuncAttributeMaxDynamicSharedMemorySize, GSMEM);
    cudaFuncSetAttribute(gemm_tc<3>, cudaFuncAttributeMaxDynamicSharedMemorySize, GSMEM);

    dim3 blkG(128);
    dim3 blk(256);
    dim3 gQKV(24, 64);           // N=3072 fused Q|K|V
    dim3 gO(8, 64);              // N=1024

    prep_k<<<12800, blk>>>(Xq, mask_aft, mask_bef, Wq, Wk, Wv, Wo);
    gemm_tc<0><<<gQKV, blkG, GSMEM>>>(nullptr);
    attn_k<<<dim3(16, BH), blkG, ATT_SMEM>>>();
    gemm_tc<3><<<gO, blkG, GSMEM>>>(out);
}